// round 5
// baseline (speedup 1.0000x reference)
#include <cuda_runtime.h>
#include <cuda_bf16.h>

// ---------------------------------------------------------------------------
// Ptychography forward model (sm_103a).  10 fused 1-D FFT passes with
// transpose-on-write; FFT-256 = 16x16 four-step; packed fp32x2 math;
// in-place digit-reversed FFT-16; cross-twiddles generated by a register
// cmul chain from W256^s (no smem twiddle table).
// ---------------------------------------------------------------------------

typedef unsigned long long cpk;   // packed complex: lo=re, hi=im (f32x2)

// ---- static device scratch ----
__device__ cpk   g_g[39 * 65536];        // probe tiles after first Fx
__device__ cpk   g_psiA[256 * 65536];    // ping (128 MB)
__device__ cpk   g_psiB[256 * 65536];    // pong (128 MB)
__device__ cpk   g_tf[65536];            // angular-spectrum TF (pre-scaled 1/65536)
__device__ int2  g_ipos[32];
__device__ float2 g_frac[32];
__device__ float g_w[32][4];

// ---- packed complex helpers ----
__device__ __forceinline__ cpk mkpk(float x, float y) {
    cpk r; asm("mov.b64 %0, {%1, %2};" : "=l"(r) : "f"(x), "f"(y)); return r;
}
__device__ __forceinline__ void unpk(cpk a, float& x, float& y) {
    asm("mov.b64 {%0, %1}, %2;" : "=f"(x), "=f"(y) : "l"(a));
}
__device__ __forceinline__ cpk addpk(cpk a, cpk b) {
    cpk r; asm("add.rn.f32x2 %0, %1, %2;" : "=l"(r) : "l"(a), "l"(b)); return r;
}
__device__ __forceinline__ cpk fmapk(cpk a, cpk b, cpk c) {
    cpk r; asm("fma.rn.f32x2 %0, %1, %2, %3;" : "=l"(r) : "l"(a), "l"(b), "l"(c)); return r;
}
__device__ __forceinline__ cpk subpk(cpk a, cpk b, cpk n1) {   // a - b
    return fmapk(b, n1, a);
}
__device__ __forceinline__ cpk cmulpp(cpk a, cpk b) {          // a * b
    float ax, ay, bx, by; unpk(a, ax, ay); unpk(b, bx, by);
    return mkpk(fmaf(ax, bx, -(ay * by)), fmaf(ax, by, ay * bx));
}
__device__ __forceinline__ cpk cmulcc(cpk a, cpk b) {          // a * conj(b)
    float ax, ay, bx, by; unpk(a, ax, ay); unpk(b, bx, by);
    return mkpk(fmaf(ax, bx, ay * by), fmaf(ay, bx, -(ax * by)));
}
__device__ __forceinline__ cpk cmulk(cpk a, float bx, float by) { // a * (bx+i by)
    float ax, ay; unpk(a, ax, ay);
    return mkpk(fmaf(ax, bx, -(ay * by)), fmaf(ax, by, ay * bx));
}

// base-4 digit reversal of 4-bit index (involution)
__device__ __forceinline__ constexpr int dr4(int p) { return ((p & 3) << 2) | (p >> 2); }

template<bool INV>
__device__ __forceinline__ void btf4p(cpk& a, cpk& b, cpk& c, cpk& d, cpk n1) {
    cpk t0 = addpk(a, c), t1 = subpk(a, c, n1);
    cpk t2 = addpk(b, d), t3 = subpk(b, d, n1);
    a = addpk(t0, t2); c = subpk(t0, t2, n1);
    float x, y; unpk(t3, x, y);
    cpk u = INV ? mkpk(-y, x) : mkpk(y, -x);   // -/+ i*t3
    b = addpk(t1, u); d = subpk(t1, u, n1);
}

#define TWK(q, arr_c, arr_s) arr_c[q], (INV ? -arr_s[q] : arr_s[q])

// in-place 16-pt DFT, NATURAL input -> DIGIT-REVERSED output (pos holds k=dr(pos))
template<bool INV>
__device__ __forceinline__ void fftDR(cpk* v, cpk n1) {
    const float C1[4] = { 1.f, 0.92387953f, 0.70710678f, 0.38268343f };
    const float S1[4] = { 0.f, -0.38268343f, -0.70710678f, -0.92387953f };
    const float C2[4] = { 1.f, 0.70710678f, 0.f, -0.70710678f };
    const float S2[4] = { 0.f, -0.70710678f, -1.f, -0.70710678f };
    const float C3[4] = { 1.f, 0.38268343f, -0.70710678f, -0.92387953f };
    const float S3[4] = { 0.f, -0.92387953f, -0.70710678f, 0.38268343f };
#pragma unroll
    for (int a = 0; a < 4; a++)
        btf4p<INV>(v[a], v[a + 4], v[a + 8], v[a + 12], n1);
#pragma unroll
    for (int q = 0; q < 4; q++) {
        if (q) {
            v[4 * q + 1] = cmulk(v[4 * q + 1], TWK(q, C1, S1));
            v[4 * q + 2] = cmulk(v[4 * q + 2], TWK(q, C2, S2));
            v[4 * q + 3] = cmulk(v[4 * q + 3], TWK(q, C3, S3));
        }
        btf4p<INV>(v[4 * q], v[4 * q + 1], v[4 * q + 2], v[4 * q + 3], n1);
    }
}

// in-place 16-pt DFT, DIGIT-REVERSED input (pos holds x[dr(pos)]) -> NATURAL out
template<bool INV>
__device__ __forceinline__ void fftRD(cpk* v, cpk n1) {
    const float C1[4] = { 1.f, 0.92387953f, 0.70710678f, 0.38268343f };
    const float S1[4] = { 0.f, -0.38268343f, -0.70710678f, -0.92387953f };
    const float C2[4] = { 1.f, 0.70710678f, 0.f, -0.70710678f };
    const float S2[4] = { 0.f, -0.70710678f, -1.f, -0.70710678f };
    const float C3[4] = { 1.f, 0.38268343f, -0.70710678f, -0.92387953f };
    const float S3[4] = { 0.f, -0.92387953f, -0.70710678f, 0.38268343f };
#pragma unroll
    for (int a = 0; a < 4; a++)
        btf4p<INV>(v[4 * a], v[4 * a + 1], v[4 * a + 2], v[4 * a + 3], n1);
#pragma unroll
    for (int q = 0; q < 4; q++) {
        if (q) {
            v[q + 4]  = cmulk(v[q + 4],  TWK(q, C1, S1));
            v[q + 8]  = cmulk(v[q + 8],  TWK(q, C2, S2));
            v[q + 12] = cmulk(v[q + 12], TWK(q, C3, S3));
        }
        btf4p<INV>(v[q], v[q + 4], v[q + 8], v[q + 12], n1);
    }
}

// 256-pt transform A: natural register input -> DR register output.
// ws = W256^s; cross-twiddles generated by cmul chain. Inverse unnormalized.
template<bool INV>
__device__ __forceinline__ void transformA(cpk* v, cpk* xch, cpk ws,
                                           int s, cpk n1) {
    fftDR<INV>(v, n1);                       // v[pos] = comp k2 = dr(pos)
    cpk cur = ws;
#pragma unroll
    for (int k2 = 1; k2 < 16; k2++) {        // natural k2 order for the chain
        int pos = dr4(k2);
        v[pos] = INV ? cmulcc(v[pos], cur) : cmulpp(v[pos], cur);
        if (k2 < 15) cur = cmulpp(cur, ws);
    }
    __syncwarp();
#pragma unroll
    for (int pos = 0; pos < 16; pos++)
        xch[s * 16 + ((dr4(pos) + s) & 15)] = v[pos];
    __syncwarp();
#pragma unroll
    for (int a = 0; a < 16; a++) v[a] = xch[a * 16 + ((s + a) & 15)];
    fftDR<INV>(v, n1);                       // DR out
}

// 256-pt transform B: DR register input -> DR register output.
template<bool INV>
__device__ __forceinline__ void transformB(cpk* v, cpk* xch, cpk ws,
                                           int s, cpk n1) {
    fftRD<INV>(v, n1);                       // natural k2 at pos
    cpk cur = ws;
#pragma unroll
    for (int k2 = 1; k2 < 16; k2++) {
        v[k2] = INV ? cmulcc(v[k2], cur) : cmulpp(v[k2], cur);
        if (k2 < 15) cur = cmulpp(cur, ws);
    }
    __syncwarp();
#pragma unroll
    for (int k2 = 0; k2 < 16; k2++) xch[s * 16 + ((k2 + s) & 15)] = v[k2];
    __syncwarp();
#pragma unroll
    for (int a = 0; a < 16; a++) v[a] = xch[a * 16 + ((s + a) & 15)];
    fftDR<INV>(v, n1);                       // DR out
}

// per-thread W256^s
__device__ __forceinline__ cpk make_ws(int s) {
    float sv, cv; sincospif(-(float)s / 128.0f, &sv, &cv);
    return mkpk(cv, sv);
}

// Transposed store of 16 rows x 256 elements (DR register layout) via smem.
__device__ __forceinline__ void store_transposed(const cpk* v, cpk* buf,
                                                 cpk* gout, int row0,
                                                 int line, int s, int tid) {
    __syncthreads();
#pragma unroll
    for (int r = 0; r < 16; r++)
        buf[(s + 16 * dr4(r)) * 17 + line] = v[r];
    __syncthreads();
    int l2 = tid & 15, e0 = tid >> 4;
#pragma unroll
    for (int c = 0; c < 16; c++) {
        int e = c * 16 + e0;
        gout[e * 256 + row0 + l2] = buf[e * 17 + l2];
    }
}

// ---------------------------------------------------------------------------
__global__ void __launch_bounds__(256) kSetupPos(const float* positions,
                                                 const int* indices,
                                                 const float* opr) {
    int b = threadIdx.x;
    if (b < 32) {
        int idx = indices[b];
        float py = positions[idx * 2 + 0], px = positions[idx * 2 + 1];
        float ry = rintf(py), rx = rintf(px);
        int iy = (int)ry, ix = (int)rx;
        iy = min(max(iy, 0), 768); ix = min(max(ix, 0), 768);
        g_ipos[b] = make_int2(iy, ix);
        g_frac[b] = make_float2(py - ry, px - rx);
        for (int k = 0; k < 4; k++) g_w[b][k] = opr[idx * 4 + k];
    }
}

__global__ void __launch_bounds__(256) kSetupTF() {
    int idx = blockIdx.x * 256 + threadIdx.x;
    int i = idx >> 8, j = idx & 255;
    double fy = (double)((i < 128) ? i : i - 256) / (256.0 * 1.0e-8);
    double fx = (double)((j < 128) ? j : j - 256) / (256.0 * 1.0e-8);
    const double lam = 1.24e-10;
    double ax = lam * fx, ay = lam * fy;
    double arg = 1.0 - ax * ax - ay * ay;
    float tfx = 0.f, tfy = 0.f;
    if (arg > 0.0) {
        double ph = 2.0e-6 * (6.283185307179586 / lam) * sqrt(arg);
        tfx = (float)(cos(ph) * (1.0 / 65536.0));   // folds 2 inverse norms
        tfy = (float)(sin(ph) * (1.0 / 65536.0));
    }
    g_tf[idx] = mkpk(tfx, tfy);
}

// P0: 39 unique probe tiles (32 OPR + 7 shared modes), Fx, store [kx][y].
__global__ void __launch_bounds__(256, 4) kP0(const float* probe) {
    __shared__ cpk buf[256 * 17];
    int tid = threadIdx.x;
    const cpk n1 = mkpk(-1.f, -1.f);
    int u = blockIdx.y, row0 = blockIdx.x * 16;
    int line = tid >> 4, s = tid & 15;
    cpk ws = make_ws(s);
    int y = row0 + line;
    const float2* p = (const float2*)probe;   // (4, 8, 256, 256) complex
    cpk v[16];
    if (u < 32) {
        float w0 = g_w[u][0], w1 = g_w[u][1], w2 = g_w[u][2], w3 = g_w[u][3];
        const float2* p0 = p + y * 256;
#pragma unroll
        for (int r = 0; r < 16; r++) {
            int x = s + 16 * r;
            float2 a = p0[x], b = p0[x + 524288], c = p0[x + 1048576], d = p0[x + 1572864];
            v[r] = mkpk(fmaf(w0, a.x, fmaf(w1, b.x, fmaf(w2, c.x, w3 * d.x))),
                        fmaf(w0, a.y, fmaf(w1, b.y, fmaf(w2, c.y, w3 * d.y))));
        }
    } else {
        int m = u - 31;
        const cpk* q = (const cpk*)probe + m * 65536 + y * 256;
#pragma unroll
        for (int r = 0; r < 16; r++) v[r] = q[s + 16 * r];
    }
    transformA<false>(v, buf + line * 256, ws, s, n1);
    store_transposed(v, buf, g_g + u * 65536, row0, line, s, tid);
}

// P1: Fy, x subpixel ramp (pre-scaled 1/65536), Fy^-1, store [y][kx] -> psiA.
__global__ void __launch_bounds__(256, 4) kP1() {
    __shared__ cpk buf[256 * 17];
    __shared__ cpk phb[16], phx[16], phc[2];
    int tid = threadIdx.x;
    int t = blockIdx.y, row0 = blockIdx.x * 16;
    int b = t >> 3, m = t & 7;
    float2 fr = g_frac[b];
    if (tid < 16) {                          // e^{-2pi i fy*s/256} / 65536
        float sv, cv; sincospif(-fr.x * (float)tid / 128.0f, &sv, &cv);
        phb[tid] = mkpk(cv * (1.0f / 65536.0f), sv * (1.0f / 65536.0f));
    } else if (tid < 32) {                   // e^{-2pi i fx*f(kx)} per line
        int l = tid - 16, kx = row0 + l;
        float fk = (float)((kx < 128) ? kx : kx - 256) * (1.0f / 256.0f);
        float sv, cv; sincospif(-2.0f * fr.y * fk, &sv, &cv);
        phx[l] = mkpk(cv, sv);
    } else if (tid == 32) {                  // step e^{-2pi i fy/16}
        float sv, cv; sincospif(-fr.x / 8.0f, &sv, &cv);
        phc[0] = mkpk(cv, sv);
    } else if (tid == 33) {                  // wrap corr e^{+2pi i fy}
        float sv, cv; sincospif(2.0f * fr.x, &sv, &cv);
        phc[1] = mkpk(cv, sv);
    }
    __syncthreads();
    const cpk n1 = mkpk(-1.f, -1.f);
    int line = tid >> 4, s = tid & 15;
    cpk ws = make_ws(s);
    int kx = row0 + line;
    int u = (m == 0) ? b : 31 + m;
    const cpk* src = g_g + u * 65536 + kx * 256;
    cpk v[16];
#pragma unroll
    for (int r = 0; r < 16; r++) v[r] = src[s + 16 * r];
    transformA<false>(v, buf + line * 256, ws, s, n1);
    cpk step = phc[0], corr = phc[1];
    cpk cur = cmulpp(phx[line], phb[s]);
#pragma unroll
    for (int mm = 0; mm < 16; mm++) {        // logical ky = s + 16*mm
        if (mm == 8) cur = cmulpp(cur, corr);
        v[dr4(mm)] = cmulpp(v[dr4(mm)], cur);
        cur = cmulpp(cur, step);
    }
    transformB<true>(v, buf + line * 256, ws, s, n1);
    store_transposed(v, buf, g_psiA + t * 65536, row0, line, s, tid);
}

// kMod: Fx^-1 (unnormalized), x object patch, Fx, store [kx][y].
__global__ void __launch_bounds__(256, 4) kMod(const float* object, int slice, int srcA) {
    __shared__ cpk buf[256 * 17];
    int tid = threadIdx.x;
    const cpk n1 = mkpk(-1.f, -1.f);
    const cpk* sbuf = srcA ? g_psiA : g_psiB;
    cpk* dbuf = srcA ? g_psiB : g_psiA;
    int t = blockIdx.y, row0 = blockIdx.x * 16;
    int b = t >> 3;
    int line = tid >> 4, s = tid & 15;
    cpk ws = make_ws(s);
    int y = row0 + line;
    const cpk* sp = sbuf + t * 65536 + y * 256;
    cpk v[16];
#pragma unroll
    for (int r = 0; r < 16; r++) v[r] = sp[s + 16 * r];
    transformA<true>(v, buf + line * 256, ws, s, n1);
    int2 ip = g_ipos[b];
    const cpk* op = (const cpk*)object + slice * 1048576 + (ip.x + y) * 1024 + ip.y;
#pragma unroll
    for (int pos = 0; pos < 16; pos++)
        v[pos] = cmulpp(v[pos], op[s + 16 * dr4(pos)]);
    transformB<false>(v, buf + line * 256, ws, s, n1);
    store_transposed(v, buf, dbuf + t * 65536, row0, line, s, tid);
}

// kProp: Fy, x TF (pre-scaled 1/65536), Fy^-1 (unnormalized), store [y][kx].
__global__ void __launch_bounds__(256, 4) kProp(int srcA) {
    __shared__ cpk buf[256 * 17];
    int tid = threadIdx.x;
    const cpk n1 = mkpk(-1.f, -1.f);
    const cpk* sbuf = srcA ? g_psiA : g_psiB;
    cpk* dbuf = srcA ? g_psiB : g_psiA;
    int t = blockIdx.y, row0 = blockIdx.x * 16;
    int line = tid >> 4, s = tid & 15;
    cpk ws = make_ws(s);
    int kx = row0 + line;
    const cpk* sp = sbuf + t * 65536 + kx * 256;
    cpk v[16];
#pragma unroll
    for (int r = 0; r < 16; r++) v[r] = sp[s + 16 * r];
    transformA<false>(v, buf + line * 256, ws, s, n1);
    const cpk* tfp = g_tf + kx * 256;        // TF symmetric in (ky,kx)
#pragma unroll
    for (int pos = 0; pos < 16; pos++)
        v[pos] = cmulpp(v[pos], tfp[s + 16 * dr4(pos)]);
    transformB<true>(v, buf + line * 256, ws, s, n1);
    store_transposed(v, buf, dbuf + t * 65536, row0, line, s, tid);
}

// P9: final Fy, |.|^2 over 8 modes, ortho 1/65536, fftshift remap.
__global__ void __launch_bounds__(256, 4) kFinal(float* out) {
    __shared__ cpk buf[256 * 17];
    int tid = threadIdx.x;
    const cpk n1 = mkpk(-1.f, -1.f);
    int bb = blockIdx.y, row0 = blockIdx.x * 16;
    int line = tid >> 4, s = tid & 15;
    cpk ws = make_ws(s);
    int kx = row0 + line;
    float acc[16];
#pragma unroll
    for (int r = 0; r < 16; r++) acc[r] = 0.f;
    for (int m = 0; m < 8; m++) {
        const cpk* sp = g_psiB + (bb * 8 + m) * 65536 + kx * 256;
        cpk v[16];
#pragma unroll
        for (int r = 0; r < 16; r++) v[r] = sp[s + 16 * r];
        transformA<false>(v, buf + line * 256, ws, s, n1);
#pragma unroll
        for (int pos = 0; pos < 16; pos++) {
            float x, y; unpk(v[pos], x, y);
            acc[pos] = fmaf(x, x, fmaf(y, y, acc[pos]));
        }
    }
    float* sf = (float*)buf;
    __syncthreads();
#pragma unroll
    for (int pos = 0; pos < 16; pos++) {
        int ky = s + 16 * dr4(pos);
        int yo = (ky + 128) & 255;                         // fftshift rows
        sf[yo * 17 + line] = acc[pos] * (1.0f / 65536.0f); // ortho norm
    }
    __syncthreads();
    int xb0 = (row0 + 128) & 255;                          // fftshift cols
    int l2 = tid & 15, e0 = tid >> 4;
#pragma unroll
    for (int c = 0; c < 16; c++) {
        int yy = c * 16 + e0;
        out[bb * 65536 + yy * 256 + xb0 + l2] = sf[yy * 17 + l2];
    }
}

// ---------------------------------------------------------------------------
extern "C" void kernel_launch(void* const* d_in, const int* in_sizes, int n_in,
                              void* d_out, int out_size) {
    const float* object = nullptr;    // (4,1024,1024,2)  -> 8388608
    const float* probe = nullptr;     // (4,8,256,256,2)  -> 4194304
    const float* opr = nullptr;       // (512,4)          -> 2048
    const float* positions = nullptr; // (512,2)          -> 1024
    const int*   indices = nullptr;   // (32,)            -> 32
    for (int i = 0; i < n_in; i++) {
        switch (in_sizes[i]) {
            case 8388608: object    = (const float*)d_in[i]; break;
            case 4194304: probe     = (const float*)d_in[i]; break;
            case 2048:    opr       = (const float*)d_in[i]; break;
            case 1024:    positions = (const float*)d_in[i]; break;
            case 32:      indices   = (const int*)d_in[i];   break;
        }
    }
    float* out = (float*)d_out;

    kSetupPos<<<1, 32>>>(positions, indices, opr);
    kSetupTF<<<256, 256>>>();
    kP0<<<dim3(16, 39), 256>>>(probe);
    kP1<<<dim3(16, 256), 256>>>();                  // -> psiA [y][kx]
    kMod<<<dim3(16, 256), 256>>>(object, 0, 1);     // A -> B  [kx][y]
    kProp<<<dim3(16, 256), 256>>>(0);               // B -> A  [y][kx]
    kMod<<<dim3(16, 256), 256>>>(object, 1, 1);
    kProp<<<dim3(16, 256), 256>>>(0);
    kMod<<<dim3(16, 256), 256>>>(object, 2, 1);
    kProp<<<dim3(16, 256), 256>>>(0);
    kMod<<<dim3(16, 256), 256>>>(object, 3, 1);
    kFinal<<<dim3(16, 32), 256>>>(out);             // B -> intensities
}

// round 6
// speedup vs baseline: 1.0509x; 1.0509x over previous
#include <cuda_runtime.h>
#include <cuda_bf16.h>

// ---------------------------------------------------------------------------
// Ptychography forward model (sm_103a).  10 fused 1-D FFT passes with
// transpose-on-write; FFT-256 = 16x16 four-step; packed fp32x2 math;
// in-place digit-reversed FFT-16; cross-twiddles generated by a register
// cmul chain from W256^s (no smem twiddle table).  3 CTAs/SM (no spills).
// ---------------------------------------------------------------------------

typedef unsigned long long cpk;   // packed complex: lo=re, hi=im (f32x2)

// ---- static device scratch ----
__device__ cpk   g_g[39 * 65536];        // probe tiles after first Fx
__device__ cpk   g_psiA[256 * 65536];    // ping (128 MB)
__device__ cpk   g_psiB[256 * 65536];    // pong (128 MB)
__device__ cpk   g_tf[65536];            // angular-spectrum TF (pre-scaled 1/65536)
__device__ int2  g_ipos[32];
__device__ float2 g_frac[32];
__device__ float g_w[32][4];

// ---- packed complex helpers ----
__device__ __forceinline__ cpk mkpk(float x, float y) {
    cpk r; asm("mov.b64 %0, {%1, %2};" : "=l"(r) : "f"(x), "f"(y)); return r;
}
__device__ __forceinline__ void unpk(cpk a, float& x, float& y) {
    asm("mov.b64 {%0, %1}, %2;" : "=f"(x), "=f"(y) : "l"(a));
}
__device__ __forceinline__ cpk addpk(cpk a, cpk b) {
    cpk r; asm("add.rn.f32x2 %0, %1, %2;" : "=l"(r) : "l"(a), "l"(b)); return r;
}
__device__ __forceinline__ cpk fmapk(cpk a, cpk b, cpk c) {
    cpk r; asm("fma.rn.f32x2 %0, %1, %2, %3;" : "=l"(r) : "l"(a), "l"(b), "l"(c)); return r;
}
__device__ __forceinline__ cpk subpk(cpk a, cpk b, cpk n1) {   // a - b
    return fmapk(b, n1, a);
}
__device__ __forceinline__ cpk cmulpp(cpk a, cpk b) {          // a * b
    float ax, ay, bx, by; unpk(a, ax, ay); unpk(b, bx, by);
    return mkpk(fmaf(ax, bx, -(ay * by)), fmaf(ax, by, ay * bx));
}
__device__ __forceinline__ cpk cmulcc(cpk a, cpk b) {          // a * conj(b)
    float ax, ay, bx, by; unpk(a, ax, ay); unpk(b, bx, by);
    return mkpk(fmaf(ax, bx, ay * by), fmaf(ay, bx, -(ax * by)));
}
__device__ __forceinline__ cpk cmulk(cpk a, float bx, float by) { // a * (bx+i by)
    float ax, ay; unpk(a, ax, ay);
    return mkpk(fmaf(ax, bx, -(ay * by)), fmaf(ax, by, ay * bx));
}

// base-4 digit reversal of 4-bit index (involution)
__device__ __forceinline__ constexpr int dr4(int p) { return ((p & 3) << 2) | (p >> 2); }

template<bool INV>
__device__ __forceinline__ void btf4p(cpk& a, cpk& b, cpk& c, cpk& d, cpk n1) {
    cpk t0 = addpk(a, c), t1 = subpk(a, c, n1);
    cpk t2 = addpk(b, d), t3 = subpk(b, d, n1);
    a = addpk(t0, t2); c = subpk(t0, t2, n1);
    float x, y; unpk(t3, x, y);
    cpk u = INV ? mkpk(-y, x) : mkpk(y, -x);   // -/+ i*t3
    b = addpk(t1, u); d = subpk(t1, u, n1);
}

#define TWK(q, arr_c, arr_s) arr_c[q], (INV ? -arr_s[q] : arr_s[q])

// in-place 16-pt DFT, NATURAL input -> DIGIT-REVERSED output (pos holds k=dr(pos))
template<bool INV>
__device__ __forceinline__ void fftDR(cpk* v, cpk n1) {
    const float C1[4] = { 1.f, 0.92387953f, 0.70710678f, 0.38268343f };
    const float S1[4] = { 0.f, -0.38268343f, -0.70710678f, -0.92387953f };
    const float C2[4] = { 1.f, 0.70710678f, 0.f, -0.70710678f };
    const float S2[4] = { 0.f, -0.70710678f, -1.f, -0.70710678f };
    const float C3[4] = { 1.f, 0.38268343f, -0.70710678f, -0.92387953f };
    const float S3[4] = { 0.f, -0.92387953f, -0.70710678f, 0.38268343f };
#pragma unroll
    for (int a = 0; a < 4; a++)
        btf4p<INV>(v[a], v[a + 4], v[a + 8], v[a + 12], n1);
#pragma unroll
    for (int q = 0; q < 4; q++) {
        if (q) {
            v[4 * q + 1] = cmulk(v[4 * q + 1], TWK(q, C1, S1));
            v[4 * q + 2] = cmulk(v[4 * q + 2], TWK(q, C2, S2));
            v[4 * q + 3] = cmulk(v[4 * q + 3], TWK(q, C3, S3));
        }
        btf4p<INV>(v[4 * q], v[4 * q + 1], v[4 * q + 2], v[4 * q + 3], n1);
    }
}

// in-place 16-pt DFT, DIGIT-REVERSED input (pos holds x[dr(pos)]) -> NATURAL out
template<bool INV>
__device__ __forceinline__ void fftRD(cpk* v, cpk n1) {
    const float C1[4] = { 1.f, 0.92387953f, 0.70710678f, 0.38268343f };
    const float S1[4] = { 0.f, -0.38268343f, -0.70710678f, -0.92387953f };
    const float C2[4] = { 1.f, 0.70710678f, 0.f, -0.70710678f };
    const float S2[4] = { 0.f, -0.70710678f, -1.f, -0.70710678f };
    const float C3[4] = { 1.f, 0.38268343f, -0.70710678f, -0.92387953f };
    const float S3[4] = { 0.f, -0.92387953f, -0.70710678f, 0.38268343f };
#pragma unroll
    for (int a = 0; a < 4; a++)
        btf4p<INV>(v[4 * a], v[4 * a + 1], v[4 * a + 2], v[4 * a + 3], n1);
#pragma unroll
    for (int q = 0; q < 4; q++) {
        if (q) {
            v[q + 4]  = cmulk(v[q + 4],  TWK(q, C1, S1));
            v[q + 8]  = cmulk(v[q + 8],  TWK(q, C2, S2));
            v[q + 12] = cmulk(v[q + 12], TWK(q, C3, S3));
        }
        btf4p<INV>(v[q], v[q + 4], v[q + 8], v[q + 12], n1);
    }
}

// 256-pt transform A: natural register input -> DR register output.
// ws = W256^s; cross-twiddles generated by cmul chain. Inverse unnormalized.
template<bool INV>
__device__ __forceinline__ void transformA(cpk* v, cpk* xch, cpk ws,
                                           int s, cpk n1) {
    fftDR<INV>(v, n1);                       // v[pos] = comp k2 = dr(pos)
    cpk cur = ws;
#pragma unroll
    for (int k2 = 1; k2 < 16; k2++) {        // natural k2 order for the chain
        int pos = dr4(k2);
        v[pos] = INV ? cmulcc(v[pos], cur) : cmulpp(v[pos], cur);
        if (k2 < 15) cur = cmulpp(cur, ws);
    }
    __syncwarp();
#pragma unroll
    for (int pos = 0; pos < 16; pos++)
        xch[s * 16 + ((dr4(pos) + s) & 15)] = v[pos];
    __syncwarp();
#pragma unroll
    for (int a = 0; a < 16; a++) v[a] = xch[a * 16 + ((s + a) & 15)];
    fftDR<INV>(v, n1);                       // DR out
}

// 256-pt transform B: DR register input -> DR register output.
template<bool INV>
__device__ __forceinline__ void transformB(cpk* v, cpk* xch, cpk ws,
                                           int s, cpk n1) {
    fftRD<INV>(v, n1);                       // natural k2 at pos
    cpk cur = ws;
#pragma unroll
    for (int k2 = 1; k2 < 16; k2++) {
        v[k2] = INV ? cmulcc(v[k2], cur) : cmulpp(v[k2], cur);
        if (k2 < 15) cur = cmulpp(cur, ws);
    }
    __syncwarp();
#pragma unroll
    for (int k2 = 0; k2 < 16; k2++) xch[s * 16 + ((k2 + s) & 15)] = v[k2];
    __syncwarp();
#pragma unroll
    for (int a = 0; a < 16; a++) v[a] = xch[a * 16 + ((s + a) & 15)];
    fftDR<INV>(v, n1);                       // DR out
}

// per-thread W256^s
__device__ __forceinline__ cpk make_ws(int s) {
    float sv, cv; sincospif(-(float)s / 128.0f, &sv, &cv);
    return mkpk(cv, sv);
}

// Transposed store of 16 rows x 256 elements (DR register layout) via smem.
__device__ __forceinline__ void store_transposed(const cpk* v, cpk* buf,
                                                 cpk* gout, int row0,
                                                 int line, int s, int tid) {
    __syncthreads();
#pragma unroll
    for (int r = 0; r < 16; r++)
        buf[(s + 16 * dr4(r)) * 17 + line] = v[r];
    __syncthreads();
    int l2 = tid & 15, e0 = tid >> 4;
#pragma unroll
    for (int c = 0; c < 16; c++) {
        int e = c * 16 + e0;
        gout[e * 256 + row0 + l2] = buf[e * 17 + l2];
    }
}

// ---------------------------------------------------------------------------
__global__ void __launch_bounds__(256) kSetupPos(const float* positions,
                                                 const int* indices,
                                                 const float* opr) {
    int b = threadIdx.x;
    if (b < 32) {
        int idx = indices[b];
        float py = positions[idx * 2 + 0], px = positions[idx * 2 + 1];
        float ry = rintf(py), rx = rintf(px);
        int iy = (int)ry, ix = (int)rx;
        iy = min(max(iy, 0), 768); ix = min(max(ix, 0), 768);
        g_ipos[b] = make_int2(iy, ix);
        g_frac[b] = make_float2(py - ry, px - rx);
        for (int k = 0; k < 4; k++) g_w[b][k] = opr[idx * 4 + k];
    }
}

__global__ void __launch_bounds__(256) kSetupTF() {
    int idx = blockIdx.x * 256 + threadIdx.x;
    int i = idx >> 8, j = idx & 255;
    double fy = (double)((i < 128) ? i : i - 256) / (256.0 * 1.0e-8);
    double fx = (double)((j < 128) ? j : j - 256) / (256.0 * 1.0e-8);
    const double lam = 1.24e-10;
    double ax = lam * fx, ay = lam * fy;
    double arg = 1.0 - ax * ax - ay * ay;
    float tfx = 0.f, tfy = 0.f;
    if (arg > 0.0) {
        double ph = 2.0e-6 * (6.283185307179586 / lam) * sqrt(arg);
        tfx = (float)(cos(ph) * (1.0 / 65536.0));   // folds 2 inverse norms
        tfy = (float)(sin(ph) * (1.0 / 65536.0));
    }
    g_tf[idx] = mkpk(tfx, tfy);
}

// P0: 39 unique probe tiles (32 OPR + 7 shared modes), Fx, store [kx][y].
__global__ void __launch_bounds__(256, 3) kP0(const float* probe) {
    __shared__ cpk buf[256 * 17];
    int tid = threadIdx.x;
    const cpk n1 = mkpk(-1.f, -1.f);
    int u = blockIdx.y, row0 = blockIdx.x * 16;
    int line = tid >> 4, s = tid & 15;
    cpk ws = make_ws(s);
    int y = row0 + line;
    const float2* p = (const float2*)probe;   // (4, 8, 256, 256) complex
    cpk v[16];
    if (u < 32) {
        float w0 = g_w[u][0], w1 = g_w[u][1], w2 = g_w[u][2], w3 = g_w[u][3];
        const float2* p0 = p + y * 256;
#pragma unroll
        for (int r = 0; r < 16; r++) {
            int x = s + 16 * r;
            float2 a = p0[x], b = p0[x + 524288], c = p0[x + 1048576], d = p0[x + 1572864];
            v[r] = mkpk(fmaf(w0, a.x, fmaf(w1, b.x, fmaf(w2, c.x, w3 * d.x))),
                        fmaf(w0, a.y, fmaf(w1, b.y, fmaf(w2, c.y, w3 * d.y))));
        }
    } else {
        int m = u - 31;
        const cpk* q = (const cpk*)probe + m * 65536 + y * 256;
#pragma unroll
        for (int r = 0; r < 16; r++) v[r] = q[s + 16 * r];
    }
    transformA<false>(v, buf + line * 256, ws, s, n1);
    store_transposed(v, buf, g_g + u * 65536, row0, line, s, tid);
}

// P1: Fy, x subpixel ramp (pre-scaled 1/65536), Fy^-1, store [y][kx] -> psiA.
__global__ void __launch_bounds__(256, 3) kP1() {
    __shared__ cpk buf[256 * 17];
    __shared__ cpk phb[16], phx[16], phc[2];
    int tid = threadIdx.x;
    int t = blockIdx.y, row0 = blockIdx.x * 16;
    int b = t >> 3, m = t & 7;
    float2 fr = g_frac[b];
    if (tid < 16) {                          // e^{-2pi i fy*s/256} / 65536
        float sv, cv; sincospif(-fr.x * (float)tid / 128.0f, &sv, &cv);
        phb[tid] = mkpk(cv * (1.0f / 65536.0f), sv * (1.0f / 65536.0f));
    } else if (tid < 32) {                   // e^{-2pi i fx*f(kx)} per line
        int l = tid - 16, kx = row0 + l;
        float fk = (float)((kx < 128) ? kx : kx - 256) * (1.0f / 256.0f);
        float sv, cv; sincospif(-2.0f * fr.y * fk, &sv, &cv);
        phx[l] = mkpk(cv, sv);
    } else if (tid == 32) {                  // step e^{-2pi i fy/16}
        float sv, cv; sincospif(-fr.x / 8.0f, &sv, &cv);
        phc[0] = mkpk(cv, sv);
    } else if (tid == 33) {                  // wrap corr e^{+2pi i fy}
        float sv, cv; sincospif(2.0f * fr.x, &sv, &cv);
        phc[1] = mkpk(cv, sv);
    }
    __syncthreads();
    const cpk n1 = mkpk(-1.f, -1.f);
    int line = tid >> 4, s = tid & 15;
    cpk ws = make_ws(s);
    int kx = row0 + line;
    int u = (m == 0) ? b : 31 + m;
    const cpk* src = g_g + u * 65536 + kx * 256;
    cpk v[16];
#pragma unroll
    for (int r = 0; r < 16; r++) v[r] = src[s + 16 * r];
    transformA<false>(v, buf + line * 256, ws, s, n1);
    cpk step = phc[0], corr = phc[1];
    cpk cur = cmulpp(phx[line], phb[s]);
#pragma unroll
    for (int mm = 0; mm < 16; mm++) {        // logical ky = s + 16*mm
        if (mm == 8) cur = cmulpp(cur, corr);
        v[dr4(mm)] = cmulpp(v[dr4(mm)], cur);
        cur = cmulpp(cur, step);
    }
    transformB<true>(v, buf + line * 256, ws, s, n1);
    store_transposed(v, buf, g_psiA + t * 65536, row0, line, s, tid);
}

// kMod: Fx^-1 (unnormalized), x object patch, Fx, store [kx][y].
__global__ void __launch_bounds__(256, 3) kMod(const float* object, int slice, int srcA) {
    __shared__ cpk buf[256 * 17];
    int tid = threadIdx.x;
    const cpk n1 = mkpk(-1.f, -1.f);
    const cpk* sbuf = srcA ? g_psiA : g_psiB;
    cpk* dbuf = srcA ? g_psiB : g_psiA;
    int t = blockIdx.y, row0 = blockIdx.x * 16;
    int b = t >> 3;
    int line = tid >> 4, s = tid & 15;
    cpk ws = make_ws(s);
    int y = row0 + line;
    const cpk* sp = sbuf + t * 65536 + y * 256;
    cpk v[16];
#pragma unroll
    for (int r = 0; r < 16; r++) v[r] = sp[s + 16 * r];
    transformA<true>(v, buf + line * 256, ws, s, n1);
    int2 ip = g_ipos[b];
    const cpk* op = (const cpk*)object + slice * 1048576 + (ip.x + y) * 1024 + ip.y;
#pragma unroll
    for (int pos = 0; pos < 16; pos++)
        v[pos] = cmulpp(v[pos], op[s + 16 * dr4(pos)]);
    transformB<false>(v, buf + line * 256, ws, s, n1);
    store_transposed(v, buf, dbuf + t * 65536, row0, line, s, tid);
}

// kProp: Fy, x TF (pre-scaled 1/65536), Fy^-1 (unnormalized), store [y][kx].
__global__ void __launch_bounds__(256, 3) kProp(int srcA) {
    __shared__ cpk buf[256 * 17];
    int tid = threadIdx.x;
    const cpk n1 = mkpk(-1.f, -1.f);
    const cpk* sbuf = srcA ? g_psiA : g_psiB;
    cpk* dbuf = srcA ? g_psiB : g_psiA;
    int t = blockIdx.y, row0 = blockIdx.x * 16;
    int line = tid >> 4, s = tid & 15;
    cpk ws = make_ws(s);
    int kx = row0 + line;
    const cpk* sp = sbuf + t * 65536 + kx * 256;
    cpk v[16];
#pragma unroll
    for (int r = 0; r < 16; r++) v[r] = sp[s + 16 * r];
    transformA<false>(v, buf + line * 256, ws, s, n1);
    const cpk* tfp = g_tf + kx * 256;        // TF symmetric in (ky,kx)
#pragma unroll
    for (int pos = 0; pos < 16; pos++)
        v[pos] = cmulpp(v[pos], tfp[s + 16 * dr4(pos)]);
    transformB<true>(v, buf + line * 256, ws, s, n1);
    store_transposed(v, buf, dbuf + t * 65536, row0, line, s, tid);
}

// P9: final Fy, |.|^2 over 8 modes, ortho 1/65536, fftshift remap.
__global__ void __launch_bounds__(256, 3) kFinal(float* out) {
    __shared__ cpk buf[256 * 17];
    int tid = threadIdx.x;
    const cpk n1 = mkpk(-1.f, -1.f);
    int bb = blockIdx.y, row0 = blockIdx.x * 16;
    int line = tid >> 4, s = tid & 15;
    cpk ws = make_ws(s);
    int kx = row0 + line;
    float acc[16];
#pragma unroll
    for (int r = 0; r < 16; r++) acc[r] = 0.f;
    for (int m = 0; m < 8; m++) {
        const cpk* sp = g_psiB + (bb * 8 + m) * 65536 + kx * 256;
        cpk v[16];
#pragma unroll
        for (int r = 0; r < 16; r++) v[r] = sp[s + 16 * r];
        transformA<false>(v, buf + line * 256, ws, s, n1);
#pragma unroll
        for (int pos = 0; pos < 16; pos++) {
            float x, y; unpk(v[pos], x, y);
            acc[pos] = fmaf(x, x, fmaf(y, y, acc[pos]));
        }
    }
    float* sf = (float*)buf;
    __syncthreads();
#pragma unroll
    for (int pos = 0; pos < 16; pos++) {
        int ky = s + 16 * dr4(pos);
        int yo = (ky + 128) & 255;                         // fftshift rows
        sf[yo * 17 + line] = acc[pos] * (1.0f / 65536.0f); // ortho norm
    }
    __syncthreads();
    int xb0 = (row0 + 128) & 255;                          // fftshift cols
    int l2 = tid & 15, e0 = tid >> 4;
#pragma unroll
    for (int c = 0; c < 16; c++) {
        int yy = c * 16 + e0;
        out[bb * 65536 + yy * 256 + xb0 + l2] = sf[yy * 17 + l2];
    }
}

// ---------------------------------------------------------------------------
extern "C" void kernel_launch(void* const* d_in, const int* in_sizes, int n_in,
                              void* d_out, int out_size) {
    const float* object = nullptr;    // (4,1024,1024,2)  -> 8388608
    const float* probe = nullptr;     // (4,8,256,256,2)  -> 4194304
    const float* opr = nullptr;       // (512,4)          -> 2048
    const float* positions = nullptr; // (512,2)          -> 1024
    const int*   indices = nullptr;   // (32,)            -> 32
    for (int i = 0; i < n_in; i++) {
        switch (in_sizes[i]) {
            case 8388608: object    = (const float*)d_in[i]; break;
            case 4194304: probe     = (const float*)d_in[i]; break;
            case 2048:    opr       = (const float*)d_in[i]; break;
            case 1024:    positions = (const float*)d_in[i]; break;
            case 32:      indices   = (const int*)d_in[i];   break;
        }
    }
    float* out = (float*)d_out;

    kSetupPos<<<1, 32>>>(positions, indices, opr);
    kSetupTF<<<256, 256>>>();
    kP0<<<dim3(16, 39), 256>>>(probe);
    kP1<<<dim3(16, 256), 256>>>();                  // -> psiA [y][kx]
    kMod<<<dim3(16, 256), 256>>>(object, 0, 1);     // A -> B  [kx][y]
    kProp<<<dim3(16, 256), 256>>>(0);               // B -> A  [y][kx]
    kMod<<<dim3(16, 256), 256>>>(object, 1, 1);
    kProp<<<dim3(16, 256), 256>>>(0);
    kMod<<<dim3(16, 256), 256>>>(object, 2, 1);
    kProp<<<dim3(16, 256), 256>>>(0);
    kMod<<<dim3(16, 256), 256>>>(object, 3, 1);
    kFinal<<<dim3(16, 32), 256>>>(out);             // B -> intensities
}

// round 7
// speedup vs baseline: 1.4029x; 1.3350x over previous
#include <cuda_runtime.h>
#include <cuda_bf16.h>

// ---------------------------------------------------------------------------
// Ptychography forward model (sm_103a).  10 fused 1-D FFT passes; FFT-256 =
// 16x16 four-step in packed fp32x2; in-place digit-reversed FFT-16; chain
// twiddles.  NEW: the final fft16's exchange is MERGED with the transpose
// staging into one CTA-wide smem round-trip; the post-exchange fft16 runs in
// transposed thread roles and stores to global directly coalesced.
// ---------------------------------------------------------------------------

typedef unsigned long long cpk;   // packed complex: lo=re, hi=im (f32x2)

// ---- static device scratch ----
__device__ cpk   g_g[39 * 65536];        // probe tiles after first Fx
__device__ cpk   g_psiA[256 * 65536];    // ping (128 MB)
__device__ cpk   g_psiB[256 * 65536];    // pong (128 MB)
__device__ cpk   g_tf[65536];            // angular-spectrum TF (pre-scaled 1/65536)
__device__ int2  g_ipos[32];
__device__ float2 g_frac[32];
__device__ float g_w[32][4];

// ---- packed complex helpers ----
__device__ __forceinline__ cpk mkpk(float x, float y) {
    cpk r; asm("mov.b64 %0, {%1, %2};" : "=l"(r) : "f"(x), "f"(y)); return r;
}
__device__ __forceinline__ void unpk(cpk a, float& x, float& y) {
    asm("mov.b64 {%0, %1}, %2;" : "=f"(x), "=f"(y) : "l"(a));
}
__device__ __forceinline__ cpk addpk(cpk a, cpk b) {
    cpk r; asm("add.rn.f32x2 %0, %1, %2;" : "=l"(r) : "l"(a), "l"(b)); return r;
}
__device__ __forceinline__ cpk fmapk(cpk a, cpk b, cpk c) {
    cpk r; asm("fma.rn.f32x2 %0, %1, %2, %3;" : "=l"(r) : "l"(a), "l"(b), "l"(c)); return r;
}
__device__ __forceinline__ cpk subpk(cpk a, cpk b, cpk n1) {   // a - b
    return fmapk(b, n1, a);
}
__device__ __forceinline__ cpk cmulpp(cpk a, cpk b) {          // a * b
    float ax, ay, bx, by; unpk(a, ax, ay); unpk(b, bx, by);
    return mkpk(fmaf(ax, bx, -(ay * by)), fmaf(ax, by, ay * bx));
}
__device__ __forceinline__ cpk cmulcc(cpk a, cpk b) {          // a * conj(b)
    float ax, ay, bx, by; unpk(a, ax, ay); unpk(b, bx, by);
    return mkpk(fmaf(ax, bx, ay * by), fmaf(ay, bx, -(ax * by)));
}
__device__ __forceinline__ cpk cmulk(cpk a, float bx, float by) { // a * (bx+i by)
    float ax, ay; unpk(a, ax, ay);
    return mkpk(fmaf(ax, bx, -(ay * by)), fmaf(ax, by, ay * bx));
}

// base-4 digit reversal of 4-bit index (involution)
__device__ __forceinline__ constexpr int dr4(int p) { return ((p & 3) << 2) | (p >> 2); }

template<bool INV>
__device__ __forceinline__ void btf4p(cpk& a, cpk& b, cpk& c, cpk& d, cpk n1) {
    cpk t0 = addpk(a, c), t1 = subpk(a, c, n1);
    cpk t2 = addpk(b, d), t3 = subpk(b, d, n1);
    a = addpk(t0, t2); c = subpk(t0, t2, n1);
    float x, y; unpk(t3, x, y);
    cpk u = INV ? mkpk(-y, x) : mkpk(y, -x);   // -/+ i*t3
    b = addpk(t1, u); d = subpk(t1, u, n1);
}

#define TWK(q, arr_c, arr_s) arr_c[q], (INV ? -arr_s[q] : arr_s[q])

// in-place 16-pt DFT, NATURAL input -> DIGIT-REVERSED output (pos holds k=dr(pos))
template<bool INV>
__device__ __forceinline__ void fftDR(cpk* v, cpk n1) {
    const float C1[4] = { 1.f, 0.92387953f, 0.70710678f, 0.38268343f };
    const float S1[4] = { 0.f, -0.38268343f, -0.70710678f, -0.92387953f };
    const float C2[4] = { 1.f, 0.70710678f, 0.f, -0.70710678f };
    const float S2[4] = { 0.f, -0.70710678f, -1.f, -0.70710678f };
    const float C3[4] = { 1.f, 0.38268343f, -0.70710678f, -0.92387953f };
    const float S3[4] = { 0.f, -0.92387953f, -0.70710678f, 0.38268343f };
#pragma unroll
    for (int a = 0; a < 4; a++)
        btf4p<INV>(v[a], v[a + 4], v[a + 8], v[a + 12], n1);
#pragma unroll
    for (int q = 0; q < 4; q++) {
        if (q) {
            v[4 * q + 1] = cmulk(v[4 * q + 1], TWK(q, C1, S1));
            v[4 * q + 2] = cmulk(v[4 * q + 2], TWK(q, C2, S2));
            v[4 * q + 3] = cmulk(v[4 * q + 3], TWK(q, C3, S3));
        }
        btf4p<INV>(v[4 * q], v[4 * q + 1], v[4 * q + 2], v[4 * q + 3], n1);
    }
}

// in-place 16-pt DFT, DIGIT-REVERSED input (pos holds x[dr(pos)]) -> NATURAL out
template<bool INV>
__device__ __forceinline__ void fftRD(cpk* v, cpk n1) {
    const float C1[4] = { 1.f, 0.92387953f, 0.70710678f, 0.38268343f };
    const float S1[4] = { 0.f, -0.38268343f, -0.70710678f, -0.92387953f };
    const float C2[4] = { 1.f, 0.70710678f, 0.f, -0.70710678f };
    const float S2[4] = { 0.f, -0.70710678f, -1.f, -0.70710678f };
    const float C3[4] = { 1.f, 0.38268343f, -0.70710678f, -0.92387953f };
    const float S3[4] = { 0.f, -0.92387953f, -0.70710678f, 0.38268343f };
#pragma unroll
    for (int a = 0; a < 4; a++)
        btf4p<INV>(v[4 * a], v[4 * a + 1], v[4 * a + 2], v[4 * a + 3], n1);
#pragma unroll
    for (int q = 0; q < 4; q++) {
        if (q) {
            v[q + 4]  = cmulk(v[q + 4],  TWK(q, C1, S1));
            v[q + 8]  = cmulk(v[q + 8],  TWK(q, C2, S2));
            v[q + 12] = cmulk(v[q + 12], TWK(q, C3, S3));
        }
        btf4p<INV>(v[q], v[q + 4], v[q + 8], v[q + 12], n1);
    }
}

// Full 256-pt transform, natural in -> DR out (e = s + 16*dr4(pos)).
// Internal warp exchange through line-private smem region (stride-256).
template<bool INV>
__device__ __forceinline__ void transformA(cpk* v, cpk* xch, cpk ws,
                                           int s, cpk n1) {
    fftDR<INV>(v, n1);                       // v[pos] = comp k2 = dr(pos)
    cpk cur = ws;
#pragma unroll
    for (int k2 = 1; k2 < 16; k2++) {
        int pos = dr4(k2);
        v[pos] = INV ? cmulcc(v[pos], cur) : cmulpp(v[pos], cur);
        if (k2 < 15) cur = cmulpp(cur, ws);
    }
    __syncwarp();
#pragma unroll
    for (int pos = 0; pos < 16; pos++)
        xch[s * 16 + ((dr4(pos) + s) & 15)] = v[pos];
    __syncwarp();
#pragma unroll
    for (int a = 0; a < 16; a++) v[a] = xch[a * 16 + ((s + a) & 15)];
    fftDR<INV>(v, n1);                       // DR out
}

// Head of a merged transform, DR register input: fftRD + twiddle.
// Leaves v[k2] = twiddled component k2 (natural index).
template<bool INV>
__device__ __forceinline__ void headB(cpk* v, cpk ws, cpk n1) {
    fftRD<INV>(v, n1);
    cpk cur = ws;
#pragma unroll
    for (int k2 = 1; k2 < 16; k2++) {
        v[k2] = INV ? cmulcc(v[k2], cur) : cmulpp(v[k2], cur);
        if (k2 < 15) cur = cmulpp(cur, ws);
    }
}

// Head of a merged transform, natural register input: fftDR + twiddle.
// Leaves v[pos] = twiddled component k2 = dr4(pos).
template<bool INV>
__device__ __forceinline__ void headA(cpk* v, cpk ws, cpk n1) {
    fftDR<INV>(v, n1);
    cpk cur = ws;
#pragma unroll
    for (int k2 = 1; k2 < 16; k2++) {
        int pos = dr4(k2);
        v[pos] = INV ? cmulcc(v[pos], cur) : cmulpp(v[pos], cur);
        if (k2 < 15) cur = cmulpp(cur, ws);
    }
}

// Merged-exchange smem layout: row (k2*16 + line), stride 18 cpk (144 B,
// 16B-aligned, conflict-free for scattered 64-bit writes and 16-wide reads).
#define MROW 18

// per-thread W256^s
__device__ __forceinline__ cpk make_ws(int s) {
    float sv, cv; sincospif(-(float)s / 128.0f, &sv, &cv);
    return mkpk(cv, sv);
}

// ---------------------------------------------------------------------------
__global__ void __launch_bounds__(256) kSetupPos(const float* positions,
                                                 const int* indices,
                                                 const float* opr) {
    int b = threadIdx.x;
    if (b < 32) {
        int idx = indices[b];
        float py = positions[idx * 2 + 0], px = positions[idx * 2 + 1];
        float ry = rintf(py), rx = rintf(px);
        int iy = (int)ry, ix = (int)rx;
        iy = min(max(iy, 0), 768); ix = min(max(ix, 0), 768);
        g_ipos[b] = make_int2(iy, ix);
        g_frac[b] = make_float2(py - ry, px - rx);
        for (int k = 0; k < 4; k++) g_w[b][k] = opr[idx * 4 + k];
    }
}

__global__ void __launch_bounds__(256) kSetupTF() {
    int idx = blockIdx.x * 256 + threadIdx.x;
    int i = idx >> 8, j = idx & 255;
    double fy = (double)((i < 128) ? i : i - 256) / (256.0 * 1.0e-8);
    double fx = (double)((j < 128) ? j : j - 256) / (256.0 * 1.0e-8);
    const double lam = 1.24e-10;
    double ax = lam * fx, ay = lam * fy;
    double arg = 1.0 - ax * ax - ay * ay;
    float tfx = 0.f, tfy = 0.f;
    if (arg > 0.0) {
        double ph = 2.0e-6 * (6.283185307179586 / lam) * sqrt(arg);
        tfx = (float)(cos(ph) * (1.0 / 65536.0));   // folds 2 inverse norms
        tfy = (float)(sin(ph) * (1.0 / 65536.0));
    }
    g_tf[idx] = mkpk(tfx, tfy);
}

// P0: 39 unique probe tiles (32 OPR + 7 shared modes), Fx (merged), store [kx][y].
__global__ void __launch_bounds__(256, 3) kP0(const float* probe) {
    __shared__ cpk buf[256 * MROW];
    int tid = threadIdx.x;
    const cpk n1 = mkpk(-1.f, -1.f);
    int u = blockIdx.y, row0 = blockIdx.x * 16;
    int line = tid >> 4, s = tid & 15;
    cpk ws = make_ws(s);
    int y = row0 + line;
    const float2* p = (const float2*)probe;   // (4, 8, 256, 256) complex
    cpk v[16];
    if (u < 32) {
        float w0 = g_w[u][0], w1 = g_w[u][1], w2 = g_w[u][2], w3 = g_w[u][3];
        const float2* p0 = p + y * 256;
#pragma unroll
        for (int r = 0; r < 16; r++) {
            int x = s + 16 * r;
            float2 a = p0[x], b = p0[x + 524288], c = p0[x + 1048576], d = p0[x + 1572864];
            v[r] = mkpk(fmaf(w0, a.x, fmaf(w1, b.x, fmaf(w2, c.x, w3 * d.x))),
                        fmaf(w0, a.y, fmaf(w1, b.y, fmaf(w2, c.y, w3 * d.y))));
        }
    } else {
        int m = u - 31;
        const cpk* q = (const cpk*)probe + m * 65536 + y * 256;
#pragma unroll
        for (int r = 0; r < 16; r++) v[r] = q[s + 16 * r];
    }
    headA<false>(v, ws, n1);
#pragma unroll
    for (int pos = 0; pos < 16; pos++)
        buf[(dr4(pos) * 16 + line) * MROW + s] = v[pos];
    __syncthreads();
    cpk w[16];
#pragma unroll
    for (int a = 0; a < 16; a++) w[a] = buf[tid * MROW + a];
    fftDR<false>(w, n1);
    int nk2 = tid >> 4, nline = tid & 15;
    cpk* gout = g_g + u * 65536;
#pragma unroll
    for (int pos = 0; pos < 16; pos++)
        gout[(nk2 + 16 * dr4(pos)) * 256 + row0 + nline] = w[pos];
}

// P1: Fy (full), x ramp (pre-scaled 1/65536), Fy^-1 (merged), store [y][kx].
__global__ void __launch_bounds__(256, 3) kP1() {
    __shared__ cpk buf[256 * MROW];
    __shared__ cpk phb[16], phx[16], phc[2];
    int tid = threadIdx.x;
    int t = blockIdx.y, row0 = blockIdx.x * 16;
    int b = t >> 3, m = t & 7;
    float2 fr = g_frac[b];
    if (tid < 16) {                          // e^{-2pi i fy*s/256} / 65536
        float sv, cv; sincospif(-fr.x * (float)tid / 128.0f, &sv, &cv);
        phb[tid] = mkpk(cv * (1.0f / 65536.0f), sv * (1.0f / 65536.0f));
    } else if (tid < 32) {                   // e^{-2pi i fx*f(kx)} per line
        int l = tid - 16, kx = row0 + l;
        float fk = (float)((kx < 128) ? kx : kx - 256) * (1.0f / 256.0f);
        float sv, cv; sincospif(-2.0f * fr.y * fk, &sv, &cv);
        phx[l] = mkpk(cv, sv);
    } else if (tid == 32) {                  // step e^{-2pi i fy/16}
        float sv, cv; sincospif(-fr.x / 8.0f, &sv, &cv);
        phc[0] = mkpk(cv, sv);
    } else if (tid == 33) {                  // wrap corr e^{+2pi i fy}
        float sv, cv; sincospif(2.0f * fr.x, &sv, &cv);
        phc[1] = mkpk(cv, sv);
    }
    __syncthreads();
    const cpk n1 = mkpk(-1.f, -1.f);
    int line = tid >> 4, s = tid & 15;
    cpk ws = make_ws(s);
    int kx = row0 + line;
    int u = (m == 0) ? b : 31 + m;
    const cpk* src = g_g + u * 65536 + kx * 256;
    cpk v[16];
#pragma unroll
    for (int r = 0; r < 16; r++) v[r] = src[s + 16 * r];
    transformA<false>(v, buf + line * 256, ws, s, n1);
    cpk step = phc[0], corr = phc[1];
    cpk cur = cmulpp(phx[line], phb[s]);
#pragma unroll
    for (int mm = 0; mm < 16; mm++) {        // logical ky = s + 16*mm
        if (mm == 8) cur = cmulpp(cur, corr);
        v[dr4(mm)] = cmulpp(v[dr4(mm)], cur);
        cur = cmulpp(cur, step);
    }
    headB<true>(v, ws, n1);
    __syncthreads();                          // others done with t1 xch regions
#pragma unroll
    for (int k2 = 0; k2 < 16; k2++)
        buf[(k2 * 16 + line) * MROW + s] = v[k2];
    __syncthreads();
    cpk w[16];
#pragma unroll
    for (int a = 0; a < 16; a++) w[a] = buf[tid * MROW + a];
    fftDR<true>(w, n1);
    int nk2 = tid >> 4, nline = tid & 15;
    cpk* gout = g_psiA + t * 65536;
#pragma unroll
    for (int pos = 0; pos < 16; pos++)
        gout[(nk2 + 16 * dr4(pos)) * 256 + row0 + nline] = w[pos];
}

// kMod: Fx^-1 (full, unnorm), x object patch, Fx (merged), store [kx][y].
__global__ void __launch_bounds__(256, 3) kMod(const float* object, int slice, int srcA) {
    __shared__ cpk buf[256 * MROW];
    int tid = threadIdx.x;
    const cpk n1 = mkpk(-1.f, -1.f);
    const cpk* sbuf = srcA ? g_psiA : g_psiB;
    cpk* dbuf = srcA ? g_psiB : g_psiA;
    int t = blockIdx.y, row0 = blockIdx.x * 16;
    int b = t >> 3;
    int line = tid >> 4, s = tid & 15;
    cpk ws = make_ws(s);
    int y = row0 + line;
    const cpk* sp = sbuf + t * 65536 + y * 256;
    cpk v[16];
#pragma unroll
    for (int r = 0; r < 16; r++) v[r] = sp[s + 16 * r];
    transformA<true>(v, buf + line * 256, ws, s, n1);
    int2 ip = g_ipos[b];
    const cpk* op = (const cpk*)object + slice * 1048576 + (ip.x + y) * 1024 + ip.y;
#pragma unroll
    for (int pos = 0; pos < 16; pos++)
        v[pos] = cmulpp(v[pos], op[s + 16 * dr4(pos)]);
    headB<false>(v, ws, n1);
    __syncthreads();
#pragma unroll
    for (int k2 = 0; k2 < 16; k2++)
        buf[(k2 * 16 + line) * MROW + s] = v[k2];
    __syncthreads();
    cpk w[16];
#pragma unroll
    for (int a = 0; a < 16; a++) w[a] = buf[tid * MROW + a];
    fftDR<false>(w, n1);
    int nk2 = tid >> 4, nline = tid & 15;
    cpk* gout = dbuf + t * 65536;
#pragma unroll
    for (int pos = 0; pos < 16; pos++)
        gout[(nk2 + 16 * dr4(pos)) * 256 + row0 + nline] = w[pos];
}

// kProp: Fy (full), x TF (pre-scaled 1/65536), Fy^-1 (merged), store [y][kx].
__global__ void __launch_bounds__(256, 3) kProp(int srcA) {
    __shared__ cpk buf[256 * MROW];
    int tid = threadIdx.x;
    const cpk n1 = mkpk(-1.f, -1.f);
    const cpk* sbuf = srcA ? g_psiA : g_psiB;
    cpk* dbuf = srcA ? g_psiB : g_psiA;
    int t = blockIdx.y, row0 = blockIdx.x * 16;
    int line = tid >> 4, s = tid & 15;
    cpk ws = make_ws(s);
    int kx = row0 + line;
    const cpk* sp = sbuf + t * 65536 + kx * 256;
    cpk v[16];
#pragma unroll
    for (int r = 0; r < 16; r++) v[r] = sp[s + 16 * r];
    transformA<false>(v, buf + line * 256, ws, s, n1);
    const cpk* tfp = g_tf + kx * 256;        // TF symmetric in (ky,kx)
#pragma unroll
    for (int pos = 0; pos < 16; pos++)
        v[pos] = cmulpp(v[pos], tfp[s + 16 * dr4(pos)]);
    headB<true>(v, ws, n1);
    __syncthreads();
#pragma unroll
    for (int k2 = 0; k2 < 16; k2++)
        buf[(k2 * 16 + line) * MROW + s] = v[k2];
    __syncthreads();
    cpk w[16];
#pragma unroll
    for (int a = 0; a < 16; a++) w[a] = buf[tid * MROW + a];
    fftDR<true>(w, n1);
    int nk2 = tid >> 4, nline = tid & 15;
    cpk* gout = dbuf + t * 65536;
#pragma unroll
    for (int pos = 0; pos < 16; pos++)
        gout[(nk2 + 16 * dr4(pos)) * 256 + row0 + nline] = w[pos];
}

// P9: final Fy (merged) per mode, |.|^2 accumulated, ortho 1/65536,
//     fftshift via index remap, direct coalesced stores.
__global__ void __launch_bounds__(256, 3) kFinal(float* out) {
    __shared__ cpk buf[256 * MROW];
    int tid = threadIdx.x;
    const cpk n1 = mkpk(-1.f, -1.f);
    int bb = blockIdx.y, row0 = blockIdx.x * 16;
    int line = tid >> 4, s = tid & 15;
    cpk ws = make_ws(s);
    int kx = row0 + line;
    float acc[16];
#pragma unroll
    for (int r = 0; r < 16; r++) acc[r] = 0.f;
    for (int m = 0; m < 8; m++) {
        if (m) __syncthreads();              // readers of prev iter done
        const cpk* sp = g_psiB + (bb * 8 + m) * 65536 + kx * 256;
        cpk v[16];
#pragma unroll
        for (int r = 0; r < 16; r++) v[r] = sp[s + 16 * r];
        headA<false>(v, ws, n1);
#pragma unroll
        for (int pos = 0; pos < 16; pos++)
            buf[(dr4(pos) * 16 + line) * MROW + s] = v[pos];
        __syncthreads();
        cpk w[16];
#pragma unroll
        for (int a = 0; a < 16; a++) w[a] = buf[tid * MROW + a];
        fftDR<false>(w, n1);
#pragma unroll
        for (int pos = 0; pos < 16; pos++) {
            float x, y; unpk(w[pos], x, y);
            acc[pos] = fmaf(x, x, fmaf(y, y, acc[pos]));
        }
    }
    int nk2 = tid >> 4, nline = tid & 15;
    int xo = (row0 + nline + 128) & 255;                 // fftshift cols
    float* op = out + bb * 65536;
#pragma unroll
    for (int pos = 0; pos < 16; pos++) {
        int ky = nk2 + 16 * dr4(pos);
        int yo = (ky + 128) & 255;                       // fftshift rows
        op[yo * 256 + xo] = acc[pos] * (1.0f / 65536.0f);
    }
}

// ---------------------------------------------------------------------------
extern "C" void kernel_launch(void* const* d_in, const int* in_sizes, int n_in,
                              void* d_out, int out_size) {
    const float* object = nullptr;    // (4,1024,1024,2)  -> 8388608
    const float* probe = nullptr;     // (4,8,256,256,2)  -> 4194304
    const float* opr = nullptr;       // (512,4)          -> 2048
    const float* positions = nullptr; // (512,2)          -> 1024
    const int*   indices = nullptr;   // (32,)            -> 32
    for (int i = 0; i < n_in; i++) {
        switch (in_sizes[i]) {
            case 8388608: object    = (const float*)d_in[i]; break;
            case 4194304: probe     = (const float*)d_in[i]; break;
            case 2048:    opr       = (const float*)d_in[i]; break;
            case 1024:    positions = (const float*)d_in[i]; break;
            case 32:      indices   = (const int*)d_in[i];   break;
        }
    }
    float* out = (float*)d_out;

    kSetupPos<<<1, 32>>>(positions, indices, opr);
    kSetupTF<<<256, 256>>>();
    kP0<<<dim3(16, 39), 256>>>(probe);
    kP1<<<dim3(16, 256), 256>>>();                  // -> psiA [y][kx]
    kMod<<<dim3(16, 256), 256>>>(object, 0, 1);     // A -> B  [kx][y]
    kProp<<<dim3(16, 256), 256>>>(0);               // B -> A  [y][kx]
    kMod<<<dim3(16, 256), 256>>>(object, 1, 1);
    kProp<<<dim3(16, 256), 256>>>(0);
    kMod<<<dim3(16, 256), 256>>>(object, 2, 1);
    kProp<<<dim3(16, 256), 256>>>(0);
    kMod<<<dim3(16, 256), 256>>>(object, 3, 1);
    kFinal<<<dim3(16, 32), 256>>>(out);             // B -> intensities
}

// round 8
// speedup vs baseline: 1.4906x; 1.0625x over previous
#include <cuda_runtime.h>
#include <cuda_bf16.h>

// ---------------------------------------------------------------------------
// Ptychography forward model (sm_103a).  10 fused 1-D FFT passes; FFT-256 =
// 16x16 four-step in packed fp32x2; in-place digit-reversed FFT-16; merged
// final exchange+transpose; cross-twiddles applied via a DEPTH-4 TREE
// (k = 4a+b -> v[k] *= W^b * W^{4a}) instead of a serial 15-step chain.
// ---------------------------------------------------------------------------

typedef unsigned long long cpk;   // packed complex: lo=re, hi=im (f32x2)

// ---- static device scratch ----
__device__ cpk   g_g[39 * 65536];        // probe tiles after first Fx
__device__ cpk   g_psiA[256 * 65536];    // ping (128 MB)
__device__ cpk   g_psiB[256 * 65536];    // pong (128 MB)
__device__ cpk   g_tf[65536];            // angular-spectrum TF (pre-scaled 1/65536)
__device__ int2  g_ipos[32];
__device__ float2 g_frac[32];
__device__ float g_w[32][4];

// ---- packed complex helpers ----
__device__ __forceinline__ cpk mkpk(float x, float y) {
    cpk r; asm("mov.b64 %0, {%1, %2};" : "=l"(r) : "f"(x), "f"(y)); return r;
}
__device__ __forceinline__ void unpk(cpk a, float& x, float& y) {
    asm("mov.b64 {%0, %1}, %2;" : "=f"(x), "=f"(y) : "l"(a));
}
__device__ __forceinline__ cpk addpk(cpk a, cpk b) {
    cpk r; asm("add.rn.f32x2 %0, %1, %2;" : "=l"(r) : "l"(a), "l"(b)); return r;
}
__device__ __forceinline__ cpk fmapk(cpk a, cpk b, cpk c) {
    cpk r; asm("fma.rn.f32x2 %0, %1, %2, %3;" : "=l"(r) : "l"(a), "l"(b), "l"(c)); return r;
}
__device__ __forceinline__ cpk subpk(cpk a, cpk b, cpk n1) {   // a - b
    return fmapk(b, n1, a);
}
__device__ __forceinline__ cpk cmulpp(cpk a, cpk b) {          // a * b
    float ax, ay, bx, by; unpk(a, ax, ay); unpk(b, bx, by);
    return mkpk(fmaf(ax, bx, -(ay * by)), fmaf(ax, by, ay * bx));
}
__device__ __forceinline__ cpk cmulcc(cpk a, cpk b) {          // a * conj(b)
    float ax, ay, bx, by; unpk(a, ax, ay); unpk(b, bx, by);
    return mkpk(fmaf(ax, bx, ay * by), fmaf(ay, bx, -(ax * by)));
}
__device__ __forceinline__ cpk cmulk(cpk a, float bx, float by) { // a * (bx+i by)
    float ax, ay; unpk(a, ax, ay);
    return mkpk(fmaf(ax, bx, -(ay * by)), fmaf(ax, by, ay * bx));
}

// base-4 digit reversal of 4-bit index (involution)
__device__ __forceinline__ constexpr int dr4(int p) { return ((p & 3) << 2) | (p >> 2); }

template<bool INV>
__device__ __forceinline__ void btf4p(cpk& a, cpk& b, cpk& c, cpk& d, cpk n1) {
    cpk t0 = addpk(a, c), t1 = subpk(a, c, n1);
    cpk t2 = addpk(b, d), t3 = subpk(b, d, n1);
    a = addpk(t0, t2); c = subpk(t0, t2, n1);
    float x, y; unpk(t3, x, y);
    cpk u = INV ? mkpk(-y, x) : mkpk(y, -x);   // -/+ i*t3
    b = addpk(t1, u); d = subpk(t1, u, n1);
}

#define TWK(q, arr_c, arr_s) arr_c[q], (INV ? -arr_s[q] : arr_s[q])

// in-place 16-pt DFT, NATURAL input -> DIGIT-REVERSED output (pos holds k=dr(pos))
template<bool INV>
__device__ __forceinline__ void fftDR(cpk* v, cpk n1) {
    const float C1[4] = { 1.f, 0.92387953f, 0.70710678f, 0.38268343f };
    const float S1[4] = { 0.f, -0.38268343f, -0.70710678f, -0.92387953f };
    const float C2[4] = { 1.f, 0.70710678f, 0.f, -0.70710678f };
    const float S2[4] = { 0.f, -0.70710678f, -1.f, -0.70710678f };
    const float C3[4] = { 1.f, 0.38268343f, -0.70710678f, -0.92387953f };
    const float S3[4] = { 0.f, -0.92387953f, -0.70710678f, 0.38268343f };
#pragma unroll
    for (int a = 0; a < 4; a++)
        btf4p<INV>(v[a], v[a + 4], v[a + 8], v[a + 12], n1);
#pragma unroll
    for (int q = 0; q < 4; q++) {
        if (q) {
            v[4 * q + 1] = cmulk(v[4 * q + 1], TWK(q, C1, S1));
            v[4 * q + 2] = cmulk(v[4 * q + 2], TWK(q, C2, S2));
            v[4 * q + 3] = cmulk(v[4 * q + 3], TWK(q, C3, S3));
        }
        btf4p<INV>(v[4 * q], v[4 * q + 1], v[4 * q + 2], v[4 * q + 3], n1);
    }
}

// in-place 16-pt DFT, DIGIT-REVERSED input (pos holds x[dr(pos)]) -> NATURAL out
template<bool INV>
__device__ __forceinline__ void fftRD(cpk* v, cpk n1) {
    const float C1[4] = { 1.f, 0.92387953f, 0.70710678f, 0.38268343f };
    const float S1[4] = { 0.f, -0.38268343f, -0.70710678f, -0.92387953f };
    const float C2[4] = { 1.f, 0.70710678f, 0.f, -0.70710678f };
    const float S2[4] = { 0.f, -0.70710678f, -1.f, -0.70710678f };
    const float C3[4] = { 1.f, 0.38268343f, -0.70710678f, -0.92387953f };
    const float S3[4] = { 0.f, -0.92387953f, -0.70710678f, 0.38268343f };
#pragma unroll
    for (int a = 0; a < 4; a++)
        btf4p<INV>(v[4 * a], v[4 * a + 1], v[4 * a + 2], v[4 * a + 3], n1);
#pragma unroll
    for (int q = 0; q < 4; q++) {
        if (q) {
            v[q + 4]  = cmulk(v[q + 4],  TWK(q, C1, S1));
            v[q + 8]  = cmulk(v[q + 8],  TWK(q, C2, S2));
            v[q + 12] = cmulk(v[q + 12], TWK(q, C3, S3));
        }
        btf4p<INV>(v[q], v[q + 4], v[q + 8], v[q + 12], n1);
    }
}

// Tree-structured cross-twiddle: v[k] *= W^{s*k}, k = 4a+b decomposition.
// DRIDX: element k lives at register slot dr4(k). Depth ~6 (vs 15 chain).
template<bool INV, bool DRIDX>
__device__ __forceinline__ void twiddle16(cpk* v, cpk ws) {
    cpk w2 = cmulpp(ws, ws);
    cpk w3 = cmulpp(w2, ws);
    cpk g1 = cmulpp(w2, w2);        // W^4
    cpk g2 = cmulpp(g1, g1);        // W^8
    cpk g3 = cmulpp(g2, g1);        // W^12
#pragma unroll
    for (int k = 1; k < 16; k++) {
        int pos = DRIDX ? dr4(k) : k;
        int b = k & 3, a = k >> 2;
        if (b) {
            cpk wb = (b == 1) ? ws : (b == 2) ? w2 : w3;
            v[pos] = INV ? cmulcc(v[pos], wb) : cmulpp(v[pos], wb);
        }
        if (a) {
            cpk g = (a == 1) ? g1 : (a == 2) ? g2 : g3;
            v[pos] = INV ? cmulcc(v[pos], g) : cmulpp(v[pos], g);
        }
    }
}

// Full 256-pt transform, natural in -> DR out (e = s + 16*dr4(pos)).
template<bool INV>
__device__ __forceinline__ void transformA(cpk* v, cpk* xch, cpk ws,
                                           int s, cpk n1) {
    fftDR<INV>(v, n1);                       // v[pos] = comp k2 = dr(pos)
    twiddle16<INV, true>(v, ws);
    __syncwarp();
#pragma unroll
    for (int pos = 0; pos < 16; pos++)
        xch[s * 16 + ((dr4(pos) + s) & 15)] = v[pos];
    __syncwarp();
#pragma unroll
    for (int a = 0; a < 16; a++) v[a] = xch[a * 16 + ((s + a) & 15)];
    fftDR<INV>(v, n1);                       // DR out
}

// Heads of merged transforms: fft + tree twiddle, no exchange.
template<bool INV>
__device__ __forceinline__ void headB(cpk* v, cpk ws, cpk n1) {
    fftRD<INV>(v, n1);                       // natural k2 at pos
    twiddle16<INV, false>(v, ws);
}
template<bool INV>
__device__ __forceinline__ void headA(cpk* v, cpk ws, cpk n1) {
    fftDR<INV>(v, n1);                       // k2 = dr4(pos)
    twiddle16<INV, true>(v, ws);
}

// Merged-exchange smem layout: row (k2*16 + line), stride 18 cpk.
#define MROW 18

// per-thread W256^s
__device__ __forceinline__ cpk make_ws(int s) {
    float sv, cv; sincospif(-(float)s / 128.0f, &sv, &cv);
    return mkpk(cv, sv);
}

// ---------------------------------------------------------------------------
__global__ void __launch_bounds__(256) kSetupPos(const float* positions,
                                                 const int* indices,
                                                 const float* opr) {
    int b = threadIdx.x;
    if (b < 32) {
        int idx = indices[b];
        float py = positions[idx * 2 + 0], px = positions[idx * 2 + 1];
        float ry = rintf(py), rx = rintf(px);
        int iy = (int)ry, ix = (int)rx;
        iy = min(max(iy, 0), 768); ix = min(max(ix, 0), 768);
        g_ipos[b] = make_int2(iy, ix);
        g_frac[b] = make_float2(py - ry, px - rx);
        for (int k = 0; k < 4; k++) g_w[b][k] = opr[idx * 4 + k];
    }
}

__global__ void __launch_bounds__(256) kSetupTF() {
    int idx = blockIdx.x * 256 + threadIdx.x;
    int i = idx >> 8, j = idx & 255;
    double fy = (double)((i < 128) ? i : i - 256) / (256.0 * 1.0e-8);
    double fx = (double)((j < 128) ? j : j - 256) / (256.0 * 1.0e-8);
    const double lam = 1.24e-10;
    double ax = lam * fx, ay = lam * fy;
    double arg = 1.0 - ax * ax - ay * ay;
    float tfx = 0.f, tfy = 0.f;
    if (arg > 0.0) {
        double ph = 2.0e-6 * (6.283185307179586 / lam) * sqrt(arg);
        tfx = (float)(cos(ph) * (1.0 / 65536.0));   // folds 2 inverse norms
        tfy = (float)(sin(ph) * (1.0 / 65536.0));
    }
    g_tf[idx] = mkpk(tfx, tfy);
}

// P0: 39 unique probe tiles (32 OPR + 7 shared modes), Fx (merged), store [kx][y].
__global__ void __launch_bounds__(256, 3) kP0(const float* probe) {
    __shared__ cpk buf[256 * MROW];
    int tid = threadIdx.x;
    const cpk n1 = mkpk(-1.f, -1.f);
    int u = blockIdx.y, row0 = blockIdx.x * 16;
    int line = tid >> 4, s = tid & 15;
    cpk ws = make_ws(s);
    int y = row0 + line;
    const float2* p = (const float2*)probe;   // (4, 8, 256, 256) complex
    cpk v[16];
    if (u < 32) {
        float w0 = g_w[u][0], w1 = g_w[u][1], w2 = g_w[u][2], w3 = g_w[u][3];
        const float2* p0 = p + y * 256;
#pragma unroll
        for (int r = 0; r < 16; r++) {
            int x = s + 16 * r;
            float2 a = p0[x], b = p0[x + 524288], c = p0[x + 1048576], d = p0[x + 1572864];
            v[r] = mkpk(fmaf(w0, a.x, fmaf(w1, b.x, fmaf(w2, c.x, w3 * d.x))),
                        fmaf(w0, a.y, fmaf(w1, b.y, fmaf(w2, c.y, w3 * d.y))));
        }
    } else {
        int m = u - 31;
        const cpk* q = (const cpk*)probe + m * 65536 + y * 256;
#pragma unroll
        for (int r = 0; r < 16; r++) v[r] = q[s + 16 * r];
    }
    headA<false>(v, ws, n1);
#pragma unroll
    for (int pos = 0; pos < 16; pos++)
        buf[(dr4(pos) * 16 + line) * MROW + s] = v[pos];
    __syncthreads();
    cpk w[16];
#pragma unroll
    for (int a = 0; a < 16; a++) w[a] = buf[tid * MROW + a];
    fftDR<false>(w, n1);
    int nk2 = tid >> 4, nline = tid & 15;
    cpk* gout = g_g + u * 65536;
#pragma unroll
    for (int pos = 0; pos < 16; pos++)
        gout[(nk2 + 16 * dr4(pos)) * 256 + row0 + nline] = w[pos];
}

// P1: Fy (full), x ramp (pre-scaled 1/65536, tree powers), Fy^-1 (merged).
__global__ void __launch_bounds__(256, 3) kP1() {
    __shared__ cpk buf[256 * MROW];
    __shared__ cpk phb[16], phx[16], phc[2];
    int tid = threadIdx.x;
    int t = blockIdx.y, row0 = blockIdx.x * 16;
    int b = t >> 3, m = t & 7;
    float2 fr = g_frac[b];
    if (tid < 16) {                          // e^{-2pi i fy*s/256} / 65536
        float sv, cv; sincospif(-fr.x * (float)tid / 128.0f, &sv, &cv);
        phb[tid] = mkpk(cv * (1.0f / 65536.0f), sv * (1.0f / 65536.0f));
    } else if (tid < 32) {                   // e^{-2pi i fx*f(kx)} per line
        int l = tid - 16, kx = row0 + l;
        float fk = (float)((kx < 128) ? kx : kx - 256) * (1.0f / 256.0f);
        float sv, cv; sincospif(-2.0f * fr.y * fk, &sv, &cv);
        phx[l] = mkpk(cv, sv);
    } else if (tid == 32) {                  // step e^{-2pi i fy/16}
        float sv, cv; sincospif(-fr.x / 8.0f, &sv, &cv);
        phc[0] = mkpk(cv, sv);
    } else if (tid == 33) {                  // wrap corr e^{+2pi i fy}
        float sv, cv; sincospif(2.0f * fr.x, &sv, &cv);
        phc[1] = mkpk(cv, sv);
    }
    __syncthreads();
    const cpk n1 = mkpk(-1.f, -1.f);
    int line = tid >> 4, s = tid & 15;
    cpk ws = make_ws(s);
    int kx = row0 + line;
    int u = (m == 0) ? b : 31 + m;
    const cpk* src = g_g + u * 65536 + kx * 256;
    cpk v[16];
#pragma unroll
    for (int r = 0; r < 16; r++) v[r] = src[s + 16 * r];
    transformA<false>(v, buf + line * 256, ws, s, n1);
    {   // ramp multiply: mm = 4a+b', factor = base*step^b' * G_a (corr at a>=2)
        cpk stp = phc[0], corr = phc[1];
        cpk base = cmulpp(phx[line], phb[s]);
        cpk s2 = cmulpp(stp, stp);
        cpk rg1 = cmulpp(s2, s2);            // step^4
        cpk rg2 = cmulpp(rg1, rg1);          // step^8
        cpk rg2c = cmulpp(rg2, corr);
        cpk rg3c = cmulpp(rg2c, rg1);        // step^12 * corr
        cpk b0 = base;
        cpk b1 = cmulpp(base, stp);
        cpk b2 = cmulpp(base, s2);
        cpk b3 = cmulpp(b1, s2);
#pragma unroll
        for (int mm = 0; mm < 16; mm++) {
            int pos = dr4(mm);
            int bb = mm & 3, aa = mm >> 2;
            cpk f = (bb == 0) ? b0 : (bb == 1) ? b1 : (bb == 2) ? b2 : b3;
            v[pos] = cmulpp(v[pos], f);
            if (aa) {
                cpk g = (aa == 1) ? rg1 : (aa == 2) ? rg2c : rg3c;
                v[pos] = cmulpp(v[pos], g);
            }
        }
    }
    headB<true>(v, ws, n1);
    __syncthreads();                          // others done with t1 xch regions
#pragma unroll
    for (int k2 = 0; k2 < 16; k2++)
        buf[(k2 * 16 + line) * MROW + s] = v[k2];
    __syncthreads();
    cpk w[16];
#pragma unroll
    for (int a = 0; a < 16; a++) w[a] = buf[tid * MROW + a];
    fftDR<true>(w, n1);
    int nk2 = tid >> 4, nline = tid & 15;
    cpk* gout = g_psiA + t * 65536;
#pragma unroll
    for (int pos = 0; pos < 16; pos++)
        gout[(nk2 + 16 * dr4(pos)) * 256 + row0 + nline] = w[pos];
}

// kMod: Fx^-1 (full, unnorm), x object patch, Fx (merged), store [kx][y].
__global__ void __launch_bounds__(256, 3) kMod(const float* object, int slice, int srcA) {
    __shared__ cpk buf[256 * MROW];
    int tid = threadIdx.x;
    const cpk n1 = mkpk(-1.f, -1.f);
    const cpk* sbuf = srcA ? g_psiA : g_psiB;
    cpk* dbuf = srcA ? g_psiB : g_psiA;
    int t = blockIdx.y, row0 = blockIdx.x * 16;
    int b = t >> 3;
    int line = tid >> 4, s = tid & 15;
    cpk ws = make_ws(s);
    int y = row0 + line;
    const cpk* sp = sbuf + t * 65536 + y * 256;
    cpk v[16];
#pragma unroll
    for (int r = 0; r < 16; r++) v[r] = sp[s + 16 * r];
    transformA<true>(v, buf + line * 256, ws, s, n1);
    int2 ip = g_ipos[b];
    const cpk* op = (const cpk*)object + slice * 1048576 + (ip.x + y) * 1024 + ip.y;
#pragma unroll
    for (int pos = 0; pos < 16; pos++)
        v[pos] = cmulpp(v[pos], op[s + 16 * dr4(pos)]);
    headB<false>(v, ws, n1);
    __syncthreads();
#pragma unroll
    for (int k2 = 0; k2 < 16; k2++)
        buf[(k2 * 16 + line) * MROW + s] = v[k2];
    __syncthreads();
    cpk w[16];
#pragma unroll
    for (int a = 0; a < 16; a++) w[a] = buf[tid * MROW + a];
    fftDR<false>(w, n1);
    int nk2 = tid >> 4, nline = tid & 15;
    cpk* gout = dbuf + t * 65536;
#pragma unroll
    for (int pos = 0; pos < 16; pos++)
        gout[(nk2 + 16 * dr4(pos)) * 256 + row0 + nline] = w[pos];
}

// kProp: Fy (full), x TF (pre-scaled 1/65536), Fy^-1 (merged), store [y][kx].
__global__ void __launch_bounds__(256, 3) kProp(int srcA) {
    __shared__ cpk buf[256 * MROW];
    int tid = threadIdx.x;
    const cpk n1 = mkpk(-1.f, -1.f);
    const cpk* sbuf = srcA ? g_psiA : g_psiB;
    cpk* dbuf = srcA ? g_psiB : g_psiA;
    int t = blockIdx.y, row0 = blockIdx.x * 16;
    int line = tid >> 4, s = tid & 15;
    cpk ws = make_ws(s);
    int kx = row0 + line;
    const cpk* sp = sbuf + t * 65536 + kx * 256;
    cpk v[16];
#pragma unroll
    for (int r = 0; r < 16; r++) v[r] = sp[s + 16 * r];
    transformA<false>(v, buf + line * 256, ws, s, n1);
    const cpk* tfp = g_tf + kx * 256;        // TF symmetric in (ky,kx)
#pragma unroll
    for (int pos = 0; pos < 16; pos++)
        v[pos] = cmulpp(v[pos], tfp[s + 16 * dr4(pos)]);
    headB<true>(v, ws, n1);
    __syncthreads();
#pragma unroll
    for (int k2 = 0; k2 < 16; k2++)
        buf[(k2 * 16 + line) * MROW + s] = v[k2];
    __syncthreads();
    cpk w[16];
#pragma unroll
    for (int a = 0; a < 16; a++) w[a] = buf[tid * MROW + a];
    fftDR<true>(w, n1);
    int nk2 = tid >> 4, nline = tid & 15;
    cpk* gout = dbuf + t * 65536;
#pragma unroll
    for (int pos = 0; pos < 16; pos++)
        gout[(nk2 + 16 * dr4(pos)) * 256 + row0 + nline] = w[pos];
}

// P9: final Fy (merged) per mode, |.|^2 accumulated, ortho 1/65536,
//     fftshift via index remap, direct coalesced stores.
__global__ void __launch_bounds__(256, 3) kFinal(float* out) {
    __shared__ cpk buf[256 * MROW];
    int tid = threadIdx.x;
    const cpk n1 = mkpk(-1.f, -1.f);
    int bb = blockIdx.y, row0 = blockIdx.x * 16;
    int line = tid >> 4, s = tid & 15;
    cpk ws = make_ws(s);
    int kx = row0 + line;
    float acc[16];
#pragma unroll
    for (int r = 0; r < 16; r++) acc[r] = 0.f;
    for (int m = 0; m < 8; m++) {
        if (m) __syncthreads();              // readers of prev iter done
        const cpk* sp = g_psiB + (bb * 8 + m) * 65536 + kx * 256;
        cpk v[16];
#pragma unroll
        for (int r = 0; r < 16; r++) v[r] = sp[s + 16 * r];
        headA<false>(v, ws, n1);
#pragma unroll
        for (int pos = 0; pos < 16; pos++)
            buf[(dr4(pos) * 16 + line) * MROW + s] = v[pos];
        __syncthreads();
        cpk w[16];
#pragma unroll
        for (int a = 0; a < 16; a++) w[a] = buf[tid * MROW + a];
        fftDR<false>(w, n1);
#pragma unroll
        for (int pos = 0; pos < 16; pos++) {
            float x, y; unpk(w[pos], x, y);
            acc[pos] = fmaf(x, x, fmaf(y, y, acc[pos]));
        }
    }
    int nk2 = tid >> 4, nline = tid & 15;
    int xo = (row0 + nline + 128) & 255;                 // fftshift cols
    float* op = out + bb * 65536;
#pragma unroll
    for (int pos = 0; pos < 16; pos++) {
        int ky = nk2 + 16 * dr4(pos);
        int yo = (ky + 128) & 255;                       // fftshift rows
        op[yo * 256 + xo] = acc[pos] * (1.0f / 65536.0f);
    }
}

// ---------------------------------------------------------------------------
extern "C" void kernel_launch(void* const* d_in, const int* in_sizes, int n_in,
                              void* d_out, int out_size) {
    const float* object = nullptr;    // (4,1024,1024,2)  -> 8388608
    const float* probe = nullptr;     // (4,8,256,256,2)  -> 4194304
    const float* opr = nullptr;       // (512,4)          -> 2048
    const float* positions = nullptr; // (512,2)          -> 1024
    const int*   indices = nullptr;   // (32,)            -> 32
    for (int i = 0; i < n_in; i++) {
        switch (in_sizes[i]) {
            case 8388608: object    = (const float*)d_in[i]; break;
            case 4194304: probe     = (const float*)d_in[i]; break;
            case 2048:    opr       = (const float*)d_in[i]; break;
            case 1024:    positions = (const float*)d_in[i]; break;
            case 32:      indices   = (const int*)d_in[i];   break;
        }
    }
    float* out = (float*)d_out;

    kSetupPos<<<1, 32>>>(positions, indices, opr);
    kSetupTF<<<256, 256>>>();
    kP0<<<dim3(16, 39), 256>>>(probe);
    kP1<<<dim3(16, 256), 256>>>();                  // -> psiA [y][kx]
    kMod<<<dim3(16, 256), 256>>>(object, 0, 1);     // A -> B  [kx][y]
    kProp<<<dim3(16, 256), 256>>>(0);               // B -> A  [y][kx]
    kMod<<<dim3(16, 256), 256>>>(object, 1, 1);
    kProp<<<dim3(16, 256), 256>>>(0);
    kMod<<<dim3(16, 256), 256>>>(object, 2, 1);
    kProp<<<dim3(16, 256), 256>>>(0);
    kMod<<<dim3(16, 256), 256>>>(object, 3, 1);
    kFinal<<<dim3(16, 32), 256>>>(out);             // B -> intensities
}